// round 1
// baseline (speedup 1.0000x reference)
#include <cuda_runtime.h>
#include <stdint.h>

// Problem constants (fixed by the dataset)
#define NN 50000
#define EE 800000
#define HH 3
#define OO 64
#define FT 192   // HH*OO

// ---------------- scratch (device globals; allocation-free) ----------------
__device__ __align__(16) float g_fs[(size_t)NN * FT];
__device__ __align__(16) float g_fd[(size_t)NN * FT];
__device__ __align__(16) float g_ha[(size_t)NN * FT];
__device__ __align__(16) float g_hb[(size_t)NN * FT];
__device__ __align__(16) float g_elog[(size_t)EE * HH];
__device__ __align__(16) float g_m[(size_t)NN * HH];
__device__ __align__(16) float g_den[(size_t)NN * HH];
__device__ __align__(16) float g_pool[128 * OO];
__device__ __align__(16) float g_cnt[128];

__device__ __forceinline__ float lrelu(float x, float s) { return x > 0.f ? x : s * x; }

// float atomic max via signed/unsigned int ordering trick (init = 0xFFFFFFFF)
__device__ __forceinline__ void atomicMaxF(float* addr, float v) {
    if (v >= 0.f) atomicMax((int*)addr, __float_as_int(v));
    else          atomicMin((unsigned int*)addr, __float_as_uint(v));
}

// vectorized fp32 reduction (sm_90+): 4 floats per L2 red op
__device__ __forceinline__ void red_add_v4(float* addr, float x, float y, float z, float w) {
    asm volatile("red.global.add.v4.f32 [%0], {%1, %2, %3, %4};"
                 :: "l"(addr), "f"(x), "f"(y), "f"(z), "f"(w) : "memory");
}

// ---------------- SGEMM: C[M,Nc] = A[M,K] @ W[K,Nc] + bias ----------------
// 64x64 block tile, BK=16, 256 threads, 4x4 per thread. K in {128,192}, Nc=192.
#define BM 64
#define BN 64
#define BKK 16
__global__ void sgemm_bias(const float* __restrict__ A, const float* __restrict__ W,
                           const float* __restrict__ bias, float* __restrict__ C,
                           int M, int K, int Nc) {
    __shared__ float As[BKK][BM];
    __shared__ float Bs[BKK][BN];
    const int tid = threadIdx.x;
    const int tx = tid & 15, ty = tid >> 4;
    const int row0 = blockIdx.y * BM, col0 = blockIdx.x * BN;
    float acc[4][4] = {};

    for (int k0 = 0; k0 < K; k0 += BKK) {
        // A tile: 64 rows x 16 cols, one float4 per thread
        {
            int r = tid >> 2;
            int c = (tid & 3) << 2;
            float4 v = make_float4(0.f, 0.f, 0.f, 0.f);
            int gr = row0 + r;
            if (gr < M) v = *(const float4*)(A + (size_t)gr * K + k0 + c);
            As[c + 0][r] = v.x; As[c + 1][r] = v.y; As[c + 2][r] = v.z; As[c + 3][r] = v.w;
        }
        // B tile: 16 rows x 64 cols, one float4 per thread
        {
            int r = tid >> 4;
            int c = (tid & 15) << 2;
            float4 v = *(const float4*)(W + (size_t)(k0 + r) * Nc + col0 + c);
            *(float4*)&Bs[r][c] = v;
        }
        __syncthreads();
        #pragma unroll
        for (int k = 0; k < BKK; k++) {
            float a[4], b[4];
            *(float4*)a = *(const float4*)&As[k][ty << 2];
            *(float4*)b = *(const float4*)&Bs[k][tx << 2];
            #pragma unroll
            for (int i = 0; i < 4; i++)
                #pragma unroll
                for (int j = 0; j < 4; j++)
                    acc[i][j] = fmaf(a[i], b[j], acc[i][j]);
        }
        __syncthreads();
    }
    #pragma unroll
    for (int i = 0; i < 4; i++) {
        int gr = row0 + (ty << 2) + i;
        if (gr >= M) continue;
        int gc = col0 + (tx << 2);
        float4 o;
        o.x = acc[i][0] + bias[gc + 0];
        o.y = acc[i][1] + bias[gc + 1];
        o.z = acc[i][2] + bias[gc + 2];
        o.w = acc[i][3] + bias[gc + 3];
        *(float4*)(C + (size_t)gr * Nc + gc) = o;
    }
}

// ---------------- edge logits + segment max ----------------
// one warp per edge; lane q covers float4 chunk q of the 192-dim vector
__global__ void edge_logits_kernel(const float* __restrict__ fs, const float* __restrict__ fd,
                                   const int* __restrict__ src, const int* __restrict__ dst,
                                   const float* __restrict__ attn, float* __restrict__ logits,
                                   float* __restrict__ m, int E) {
    __shared__ float sattn[FT];
    if (threadIdx.x < FT) sattn[threadIdx.x] = attn[threadIdx.x];
    __syncthreads();
    int e = (blockIdx.x * blockDim.x + threadIdx.x) >> 5;
    int lane = threadIdx.x & 31;
    if (e >= E) return;
    int s = src[e], d = dst[e];
    const float4* ps = (const float4*)(fs + (size_t)s * FT);
    const float4* pd = (const float4*)(fd + (size_t)d * FT);
    const float4* pa = (const float4*)sattn;

    float acc0 = 0.f, acc1 = 0.f, acc2 = 0.f;
    {
        float4 a = ps[lane], b = pd[lane], t = pa[lane];
        float v = lrelu(a.x + b.x, 0.2f) * t.x + lrelu(a.y + b.y, 0.2f) * t.y
                + lrelu(a.z + b.z, 0.2f) * t.z + lrelu(a.w + b.w, 0.2f) * t.w;
        if (lane < 16) acc0 = v; else acc1 = v;
    }
    if (lane < 16) {
        float4 a = ps[32 + lane], b = pd[32 + lane], t = pa[32 + lane];
        acc2 = lrelu(a.x + b.x, 0.2f) * t.x + lrelu(a.y + b.y, 0.2f) * t.y
             + lrelu(a.z + b.z, 0.2f) * t.z + lrelu(a.w + b.w, 0.2f) * t.w;
    }
    #pragma unroll
    for (int off = 16; off; off >>= 1) {
        acc0 += __shfl_xor_sync(0xffffffffu, acc0, off);
        acc1 += __shfl_xor_sync(0xffffffffu, acc1, off);
        acc2 += __shfl_xor_sync(0xffffffffu, acc2, off);
    }
    if (lane == 0) {
        size_t be = (size_t)e * 3;
        logits[be + 0] = acc0;
        logits[be + 1] = acc1;
        logits[be + 2] = acc2;
        atomicMaxF(&m[d * 3 + 0], acc0);
        atomicMaxF(&m[d * 3 + 1], acc1);
        atomicMaxF(&m[d * 3 + 2], acc2);
    }
}

// ---------------- exp + segment sum (denominator) ----------------
__global__ void edge_exp_kernel(const int* __restrict__ dst, float* __restrict__ logits,
                                const float* __restrict__ m, float* __restrict__ den, int E) {
    int idx = blockIdx.x * blockDim.x + threadIdx.x;
    if (idx >= E * HH) return;
    int e = idx / 3, h = idx - e * 3;
    int d = dst[e];
    float ex = __expf(logits[idx] - m[d * 3 + h]);
    logits[idx] = ex;
    atomicAdd(&den[d * 3 + h], ex);
}

// ---------------- weighted aggregation: hout[dst] += alpha * fs[src] ----------------
__global__ void edge_aggregate_kernel(const float* __restrict__ fs,
                                      const int* __restrict__ src, const int* __restrict__ dst,
                                      const float* __restrict__ ex, const float* __restrict__ den,
                                      float* __restrict__ hout, int E) {
    int e = (blockIdx.x * blockDim.x + threadIdx.x) >> 5;
    int lane = threadIdx.x & 31;
    if (e >= E) return;
    int s = src[e], d = dst[e];
    size_t be = (size_t)e * 3;
    float w0 = ex[be + 0] / fmaxf(den[d * 3 + 0], 1e-9f);
    float w1 = ex[be + 1] / fmaxf(den[d * 3 + 1], 1e-9f);
    float w2 = ex[be + 2] / fmaxf(den[d * 3 + 2], 1e-9f);
    const float4* ps = (const float4*)(fs + (size_t)s * FT);
    float* po = hout + (size_t)d * FT;
    {
        float4 a = ps[lane];
        float w = (lane < 16) ? w0 : w1;
        red_add_v4(po + (lane << 2), a.x * w, a.y * w, a.z * w, a.w * w);
    }
    if (lane < 16) {
        float4 a = ps[32 + lane];
        red_add_v4(po + 128 + (lane << 2), a.x * w2, a.y * w2, a.z * w2, a.w * w2);
    }
}

// ---------------- head-mean + per-graph pooling ----------------
__global__ void pool_kernel(const float* __restrict__ h, const int* __restrict__ gid,
                            float* __restrict__ pool, float* __restrict__ cnt, int N) {
    int idx = blockIdx.x * blockDim.x + threadIdx.x;
    if (idx >= N * OO) return;
    int n = idx >> 6, k = idx & 63;
    const float* p = h + (size_t)n * FT;
    float v = (p[k] + p[64 + k] + p[128 + k]) * (1.0f / 3.0f);
    int g = gid[n];
    atomicAdd(&pool[g * OO + k], v);
    if (k == 0) atomicAdd(&cnt[g], 1.0f);
}

// ---------------- final MLP: 64 -> 64 -> 32 -> 2, leaky 0.01 ----------------
__global__ void mlp_kernel(const float* __restrict__ pool, const float* __restrict__ cnt,
                           const float* __restrict__ W1, const float* __restrict__ b1,
                           const float* __restrict__ W2, const float* __restrict__ b2,
                           const float* __restrict__ W3, const float* __restrict__ b3,
                           float* __restrict__ out) {
    int g = blockIdx.x;
    int j = threadIdx.x;  // 64 threads
    __shared__ float gv[64], t1[64], t2[32];
    float c = fmaxf(cnt[g], 1.0f);
    gv[j] = pool[g * OO + j] / c;
    __syncthreads();
    float a = b1[j];
    #pragma unroll 8
    for (int k = 0; k < 64; k++) a = fmaf(gv[k], W1[k * 64 + j], a);
    t1[j] = lrelu(a, 0.01f);
    __syncthreads();
    if (j < 32) {
        float a2 = b2[j];
        #pragma unroll 8
        for (int k = 0; k < 64; k++) a2 = fmaf(t1[k], W2[k * 32 + j], a2);
        t2[j] = lrelu(a2, 0.01f);
    }
    __syncthreads();
    if (j < 2) {
        float a3 = b3[j];
        #pragma unroll
        for (int k = 0; k < 32; k++) a3 = fmaf(t2[k], W3[k * 2 + j], a3);
        out[g * 2 + j] = lrelu(a3, 0.01f);
    }
}

// ---------------- launcher ----------------
extern "C" void kernel_launch(void* const* d_in, const int* in_sizes, int n_in,
                              void* d_out, int out_size) {
    const float* x   = (const float*)d_in[0];
    const int*   src = (const int*)d_in[1];
    const int*   dst = (const int*)d_in[2];
    const int*   gid = (const int*)d_in[3];
    // d_in[4] = n_graphs (scalar) — derived from out_size instead
    const float* Wsrc[3] = {(const float*)d_in[5],  (const float*)d_in[10], (const float*)d_in[15]};
    const float* bsrc[3] = {(const float*)d_in[6],  (const float*)d_in[11], (const float*)d_in[16]};
    const float* Wdst[3] = {(const float*)d_in[7],  (const float*)d_in[12], (const float*)d_in[17]};
    const float* bdst[3] = {(const float*)d_in[8],  (const float*)d_in[13], (const float*)d_in[18]};
    const float* attn[3] = {(const float*)d_in[9],  (const float*)d_in[14], (const float*)d_in[19]};
    const float* W1 = (const float*)d_in[20];
    const float* b1 = (const float*)d_in[21];
    const float* W2 = (const float*)d_in[22];
    const float* b2 = (const float*)d_in[23];
    const float* W3 = (const float*)d_in[24];
    const float* b3 = (const float*)d_in[25];

    const int N  = in_sizes[0] / 128;
    const int E  = in_sizes[1];
    const int ng = out_size / 2;

    float *fs, *fd, *ha, *hb, *elog, *m, *den, *pool, *cnt;
    cudaGetSymbolAddress((void**)&fs,   g_fs);
    cudaGetSymbolAddress((void**)&fd,   g_fd);
    cudaGetSymbolAddress((void**)&ha,   g_ha);
    cudaGetSymbolAddress((void**)&hb,   g_hb);
    cudaGetSymbolAddress((void**)&elog, g_elog);
    cudaGetSymbolAddress((void**)&m,    g_m);
    cudaGetSymbolAddress((void**)&den,  g_den);
    cudaGetSymbolAddress((void**)&pool, g_pool);
    cudaGetSymbolAddress((void**)&cnt,  g_cnt);

    const float* hin = x;
    int Fin = 128;
    float* houts[3] = {ha, hb, ha};
    const int blocksW = (E + 7) / 8;          // 1 warp per edge, 8 warps/block
    const int blocksE3 = (E * HH + 255) / 256;

    for (int l = 0; l < 3; l++) {
        dim3 gg(FT / BN, (N + BM - 1) / BM);
        sgemm_bias<<<gg, 256>>>(hin, Wsrc[l], bsrc[l], fs, N, Fin, FT);
        sgemm_bias<<<gg, 256>>>(hin, Wdst[l], bdst[l], fd, N, Fin, FT);
        cudaMemsetAsync(m,   0xFF, (size_t)N * HH * sizeof(float), 0);
        cudaMemsetAsync(den, 0,    (size_t)N * HH * sizeof(float), 0);
        edge_logits_kernel<<<blocksW, 256>>>(fs, fd, src, dst, attn[l], elog, m, E);
        edge_exp_kernel<<<blocksE3, 256>>>(dst, elog, m, den, E);
        float* ho = houts[l];
        cudaMemsetAsync(ho, 0, (size_t)N * FT * sizeof(float), 0);
        edge_aggregate_kernel<<<blocksW, 256>>>(fs, src, dst, elog, den, ho, E);
        hin = ho;
        Fin = FT;
    }

    cudaMemsetAsync(pool, 0, 128 * OO * sizeof(float), 0);
    cudaMemsetAsync(cnt,  0, 128 * sizeof(float), 0);
    pool_kernel<<<(N * OO + 255) / 256, 256>>>(hin, gid, pool, cnt, N);
    mlp_kernel<<<ng, 64>>>(pool, cnt, W1, b1, W2, b2, W3, b3, (float*)d_out);
}

// round 2
// speedup vs baseline: 1.1276x; 1.1276x over previous
#include <cuda_runtime.h>
#include <stdint.h>

// Problem constants (fixed by the dataset)
#define NN 50000
#define EE 800000
#define HH 3
#define OO 64
#define FT 192   // HH*OO

// ---------------- scratch (device globals; allocation-free) ----------------
__device__ __align__(16) float g_fs[(size_t)NN * FT];
__device__ __align__(16) float g_fd[(size_t)NN * FT];
__device__ __align__(16) float g_ha[(size_t)NN * FT];
__device__ __align__(16) float g_hb[(size_t)NN * FT];
__device__ __align__(16) float g_elog[(size_t)EE * HH];
__device__ __align__(16) float g_m[(size_t)NN * HH];
__device__ __align__(16) float g_den[(size_t)NN * HH];
__device__ __align__(16) float g_pool[128 * OO];
__device__ __align__(16) float g_cnt[128];

__device__ __forceinline__ float lrelu(float x, float s) { return x > 0.f ? x : s * x; }

// float atomic max via signed/unsigned int ordering trick (init = 0xFFFFFFFF)
__device__ __forceinline__ void atomicMaxF(float* addr, float v) {
    if (v >= 0.f) atomicMax((int*)addr, __float_as_int(v));
    else          atomicMin((unsigned int*)addr, __float_as_uint(v));
}

// vectorized fp32 reduction (sm_90+): 4 floats per L2 red op
__device__ __forceinline__ void red_add_v4(float* addr, float x, float y, float z, float w) {
    asm volatile("red.global.add.v4.f32 [%0], {%1, %2, %3, %4};"
                 :: "l"(addr), "f"(x), "f"(y), "f"(z), "f"(w) : "memory");
}

__device__ __forceinline__ uint32_t f2tf32(float f) {
    uint32_t u;
    asm("cvt.rna.tf32.f32 %0, %1;" : "=r"(u) : "f"(f));
    return u;
}

// ---------------- TF32 tensor-core GEMM: C[M,Nc] = A[M,K] @ W[K,Nc] + bias ----
// Tile 128x64x32, 256 threads (8 warps, 4x2 warp grid), warp tile 32x32.
// mma.sync.aligned.m16n8k8.row.col.f32.tf32.tf32.f32, fp32 accumulate.
// Shared k-major with stride % 32 == 8 -> fragment LDS bank = 8*tig + gid (unique).
#define GBM 128
#define GBN 64
#define GBK 32
#define ASTR 136   // 136 % 32 == 8
#define BSTR 72    // 72  % 32 == 8

__global__ __launch_bounds__(256) void gemm_tf32(
    const float* __restrict__ A, const float* __restrict__ W,
    const float* __restrict__ bias, float* __restrict__ C,
    int M, int K, int Nc)
{
    __shared__ uint32_t As[GBK][ASTR];   // [k][m]
    __shared__ uint32_t Bs[GBK][BSTR];   // [k][n]

    const int tid  = threadIdx.x;
    const int wid  = tid >> 5;
    const int lane = tid & 31;
    const int warpM = wid >> 1;          // 0..3 -> 32-row slice
    const int warpN = wid & 1;           // 0..1 -> 32-col slice
    const int gid = lane >> 2;           // 0..7
    const int tig = lane & 3;            // 0..3
    const int row0 = blockIdx.y * GBM;
    const int col0 = blockIdx.x * GBN;

    float c[2][4][4] = {};               // [mi][ni][frag]

    for (int k0 = 0; k0 < K; k0 += GBK) {
        // ---- stage A tile: 128 rows x 32 k. warp w owns k-chunk [4w,4w+4), lane = row.
        #pragma unroll
        for (int p = 0; p < 4; p++) {
            int r = p * 32 + lane;
            int grow = row0 + r;
            float4 v = make_float4(0.f, 0.f, 0.f, 0.f);
            if (grow < M) v = *(const float4*)(A + (size_t)grow * K + k0 + wid * 4);
            As[wid * 4 + 0][r] = f2tf32(v.x);
            As[wid * 4 + 1][r] = f2tf32(v.y);
            As[wid * 4 + 2][r] = f2tf32(v.z);
            As[wid * 4 + 3][r] = f2tf32(v.w);
        }
        // ---- stage B tile: 32 k x 64 n. lane = k row, warp w owns n-chunk.
        #pragma unroll
        for (int p = 0; p < 2; p++) {
            int n4 = wid + 8 * p;        // 0..15
            float4 v = *(const float4*)(W + (size_t)(k0 + lane) * Nc + col0 + n4 * 4);
            Bs[lane][n4 * 4 + 0] = f2tf32(v.x);
            Bs[lane][n4 * 4 + 1] = f2tf32(v.y);
            Bs[lane][n4 * 4 + 2] = f2tf32(v.z);
            Bs[lane][n4 * 4 + 3] = f2tf32(v.w);
        }
        __syncthreads();

        #pragma unroll
        for (int ks = 0; ks < 4; ks++) {
            const int kk = ks * 8;
            uint32_t a[2][4], b[4][2];
            #pragma unroll
            for (int mi = 0; mi < 2; mi++) {
                int rb = warpM * 32 + mi * 16;
                a[mi][0] = As[kk + tig][rb + gid];
                a[mi][1] = As[kk + tig][rb + gid + 8];
                a[mi][2] = As[kk + tig + 4][rb + gid];
                a[mi][3] = As[kk + tig + 4][rb + gid + 8];
            }
            #pragma unroll
            for (int ni = 0; ni < 4; ni++) {
                int cb = warpN * 32 + ni * 8;
                b[ni][0] = Bs[kk + tig][cb + gid];
                b[ni][1] = Bs[kk + tig + 4][cb + gid];
            }
            #pragma unroll
            for (int mi = 0; mi < 2; mi++)
                #pragma unroll
                for (int ni = 0; ni < 4; ni++)
                    asm volatile(
                        "mma.sync.aligned.m16n8k8.row.col.f32.tf32.tf32.f32 "
                        "{%0,%1,%2,%3}, {%4,%5,%6,%7}, {%8,%9}, {%0,%1,%2,%3};"
                        : "+f"(c[mi][ni][0]), "+f"(c[mi][ni][1]),
                          "+f"(c[mi][ni][2]), "+f"(c[mi][ni][3])
                        : "r"(a[mi][0]), "r"(a[mi][1]), "r"(a[mi][2]), "r"(a[mi][3]),
                          "r"(b[ni][0]), "r"(b[ni][1]));
        }
        __syncthreads();
    }

    // ---- epilogue: c0/c1 at (gid, tig*2 .. +1), c2/c3 at (gid+8, ...)
    #pragma unroll
    for (int mi = 0; mi < 2; mi++) {
        #pragma unroll
        for (int ni = 0; ni < 4; ni++) {
            int gcol = col0 + warpN * 32 + ni * 8 + tig * 2;
            float bx = bias[gcol], by = bias[gcol + 1];
            int r0 = row0 + warpM * 32 + mi * 16 + gid;
            if (r0 < M) {
                float2 o = make_float2(c[mi][ni][0] + bx, c[mi][ni][1] + by);
                *(float2*)(C + (size_t)r0 * Nc + gcol) = o;
            }
            int r1 = r0 + 8;
            if (r1 < M) {
                float2 o = make_float2(c[mi][ni][2] + bx, c[mi][ni][3] + by);
                *(float2*)(C + (size_t)r1 * Nc + gcol) = o;
            }
        }
    }
}

// ---------------- edge logits + segment max ----------------
// one warp per edge; lane q covers float4 chunk q of the 192-dim vector
__global__ void edge_logits_kernel(const float* __restrict__ fs, const float* __restrict__ fd,
                                   const int* __restrict__ src, const int* __restrict__ dst,
                                   const float* __restrict__ attn, float* __restrict__ logits,
                                   float* __restrict__ m, int E) {
    __shared__ float sattn[FT];
    if (threadIdx.x < FT) sattn[threadIdx.x] = attn[threadIdx.x];
    __syncthreads();
    int e = (blockIdx.x * blockDim.x + threadIdx.x) >> 5;
    int lane = threadIdx.x & 31;
    if (e >= E) return;
    int s = src[e], d = dst[e];
    const float4* ps = (const float4*)(fs + (size_t)s * FT);
    const float4* pd = (const float4*)(fd + (size_t)d * FT);
    const float4* pa = (const float4*)sattn;

    float acc0 = 0.f, acc1 = 0.f, acc2 = 0.f;
    {
        float4 a = ps[lane], b = pd[lane], t = pa[lane];
        float v = lrelu(a.x + b.x, 0.2f) * t.x + lrelu(a.y + b.y, 0.2f) * t.y
                + lrelu(a.z + b.z, 0.2f) * t.z + lrelu(a.w + b.w, 0.2f) * t.w;
        if (lane < 16) acc0 = v; else acc1 = v;
    }
    if (lane < 16) {
        float4 a = ps[32 + lane], b = pd[32 + lane], t = pa[32 + lane];
        acc2 = lrelu(a.x + b.x, 0.2f) * t.x + lrelu(a.y + b.y, 0.2f) * t.y
             + lrelu(a.z + b.z, 0.2f) * t.z + lrelu(a.w + b.w, 0.2f) * t.w;
    }
    #pragma unroll
    for (int off = 16; off; off >>= 1) {
        acc0 += __shfl_xor_sync(0xffffffffu, acc0, off);
        acc1 += __shfl_xor_sync(0xffffffffu, acc1, off);
        acc2 += __shfl_xor_sync(0xffffffffu, acc2, off);
    }
    if (lane == 0) {
        size_t be = (size_t)e * 3;
        logits[be + 0] = acc0;
        logits[be + 1] = acc1;
        logits[be + 2] = acc2;
        atomicMaxF(&m[d * 3 + 0], acc0);
        atomicMaxF(&m[d * 3 + 1], acc1);
        atomicMaxF(&m[d * 3 + 2], acc2);
    }
}

// ---------------- exp + segment sum (denominator) ----------------
__global__ void edge_exp_kernel(const int* __restrict__ dst, float* __restrict__ logits,
                                const float* __restrict__ m, float* __restrict__ den, int E) {
    int idx = blockIdx.x * blockDim.x + threadIdx.x;
    if (idx >= E * HH) return;
    int e = idx / 3, h = idx - e * 3;
    int d = dst[e];
    float ex = __expf(logits[idx] - m[d * 3 + h]);
    logits[idx] = ex;
    atomicAdd(&den[d * 3 + h], ex);
}

// ---------------- weighted aggregation: hout[dst] += alpha * fs[src] ----------------
__global__ void edge_aggregate_kernel(const float* __restrict__ fs,
                                      const int* __restrict__ src, const int* __restrict__ dst,
                                      const float* __restrict__ ex, const float* __restrict__ den,
                                      float* __restrict__ hout, int E) {
    int e = (blockIdx.x * blockDim.x + threadIdx.x) >> 5;
    int lane = threadIdx.x & 31;
    if (e >= E) return;
    int s = src[e], d = dst[e];
    size_t be = (size_t)e * 3;
    float w0 = ex[be + 0] / fmaxf(den[d * 3 + 0], 1e-9f);
    float w1 = ex[be + 1] / fmaxf(den[d * 3 + 1], 1e-9f);
    float w2 = ex[be + 2] / fmaxf(den[d * 3 + 2], 1e-9f);
    const float4* ps = (const float4*)(fs + (size_t)s * FT);
    float* po = hout + (size_t)d * FT;
    {
        float4 a = ps[lane];
        float w = (lane < 16) ? w0 : w1;
        red_add_v4(po + (lane << 2), a.x * w, a.y * w, a.z * w, a.w * w);
    }
    if (lane < 16) {
        float4 a = ps[32 + lane];
        red_add_v4(po + 128 + (lane << 2), a.x * w2, a.y * w2, a.z * w2, a.w * w2);
    }
}

// ---------------- head-mean + per-graph pooling ----------------
__global__ void pool_kernel(const float* __restrict__ h, const int* __restrict__ gid,
                            float* __restrict__ pool, float* __restrict__ cnt, int N) {
    int idx = blockIdx.x * blockDim.x + threadIdx.x;
    if (idx >= N * OO) return;
    int n = idx >> 6, k = idx & 63;
    const float* p = h + (size_t)n * FT;
    float v = (p[k] + p[64 + k] + p[128 + k]) * (1.0f / 3.0f);
    int g = gid[n];
    atomicAdd(&pool[g * OO + k], v);
    if (k == 0) atomicAdd(&cnt[g], 1.0f);
}

// ---------------- final MLP: 64 -> 64 -> 32 -> 2, leaky 0.01 ----------------
__global__ void mlp_kernel(const float* __restrict__ pool, const float* __restrict__ cnt,
                           const float* __restrict__ W1, const float* __restrict__ b1,
                           const float* __restrict__ W2, const float* __restrict__ b2,
                           const float* __restrict__ W3, const float* __restrict__ b3,
                           float* __restrict__ out) {
    int g = blockIdx.x;
    int j = threadIdx.x;  // 64 threads
    __shared__ float gv[64], t1[64], t2[32];
    float c = fmaxf(cnt[g], 1.0f);
    gv[j] = pool[g * OO + j] / c;
    __syncthreads();
    float a = b1[j];
    #pragma unroll 8
    for (int k = 0; k < 64; k++) a = fmaf(gv[k], W1[k * 64 + j], a);
    t1[j] = lrelu(a, 0.01f);
    __syncthreads();
    if (j < 32) {
        float a2 = b2[j];
        #pragma unroll 8
        for (int k = 0; k < 64; k++) a2 = fmaf(t1[k], W2[k * 32 + j], a2);
        t2[j] = lrelu(a2, 0.01f);
    }
    __syncthreads();
    if (j < 2) {
        float a3 = b3[j];
        #pragma unroll
        for (int k = 0; k < 32; k++) a3 = fmaf(t2[k], W3[k * 2 + j], a3);
        out[g * 2 + j] = lrelu(a3, 0.01f);
    }
}

// ---------------- launcher ----------------
extern "C" void kernel_launch(void* const* d_in, const int* in_sizes, int n_in,
                              void* d_out, int out_size) {
    const float* x   = (const float*)d_in[0];
    const int*   src = (const int*)d_in[1];
    const int*   dst = (const int*)d_in[2];
    const int*   gid = (const int*)d_in[3];
    // d_in[4] = n_graphs (scalar) — derived from out_size instead
    const float* Wsrc[3] = {(const float*)d_in[5],  (const float*)d_in[10], (const float*)d_in[15]};
    const float* bsrc[3] = {(const float*)d_in[6],  (const float*)d_in[11], (const float*)d_in[16]};
    const float* Wdst[3] = {(const float*)d_in[7],  (const float*)d_in[12], (const float*)d_in[17]};
    const float* bdst[3] = {(const float*)d_in[8],  (const float*)d_in[13], (const float*)d_in[18]};
    const float* attn[3] = {(const float*)d_in[9],  (const float*)d_in[14], (const float*)d_in[19]};
    const float* W1 = (const float*)d_in[20];
    const float* b1 = (const float*)d_in[21];
    const float* W2 = (const float*)d_in[22];
    const float* b2 = (const float*)d_in[23];
    const float* W3 = (const float*)d_in[24];
    const float* b3 = (const float*)d_in[25];

    const int N  = in_sizes[0] / 128;
    const int E  = in_sizes[1];
    const int ng = out_size / 2;

    float *fs, *fd, *ha, *hb, *elog, *m, *den, *pool, *cnt;
    cudaGetSymbolAddress((void**)&fs,   g_fs);
    cudaGetSymbolAddress((void**)&fd,   g_fd);
    cudaGetSymbolAddress((void**)&ha,   g_ha);
    cudaGetSymbolAddress((void**)&hb,   g_hb);
    cudaGetSymbolAddress((void**)&elog, g_elog);
    cudaGetSymbolAddress((void**)&m,    g_m);
    cudaGetSymbolAddress((void**)&den,  g_den);
    cudaGetSymbolAddress((void**)&pool, g_pool);
    cudaGetSymbolAddress((void**)&cnt,  g_cnt);

    const float* hin = x;
    int Fin = 128;
    float* houts[3] = {ha, hb, ha};
    const int blocksW = (E + 7) / 8;          // 1 warp per edge, 8 warps/block
    const int blocksE3 = (E * HH + 255) / 256;

    for (int l = 0; l < 3; l++) {
        dim3 gg(FT / GBN, (N + GBM - 1) / GBM);
        gemm_tf32<<<gg, 256>>>(hin, Wsrc[l], bsrc[l], fs, N, Fin, FT);
        gemm_tf32<<<gg, 256>>>(hin, Wdst[l], bdst[l], fd, N, Fin, FT);
        cudaMemsetAsync(m,   0xFF, (size_t)N * HH * sizeof(float), 0);
        cudaMemsetAsync(den, 0,    (size_t)N * HH * sizeof(float), 0);
        edge_logits_kernel<<<blocksW, 256>>>(fs, fd, src, dst, attn[l], elog, m, E);
        edge_exp_kernel<<<blocksE3, 256>>>(dst, elog, m, den, E);
        float* ho = houts[l];
        cudaMemsetAsync(ho, 0, (size_t)N * FT * sizeof(float), 0);
        edge_aggregate_kernel<<<blocksW, 256>>>(fs, src, dst, elog, den, ho, E);
        hin = ho;
        Fin = FT;
    }

    cudaMemsetAsync(pool, 0, 128 * OO * sizeof(float), 0);
    cudaMemsetAsync(cnt,  0, 128 * sizeof(float), 0);
    pool_kernel<<<(N * OO + 255) / 256, 256>>>(hin, gid, pool, cnt, N);
    mlp_kernel<<<ng, 64>>>(pool, cnt, W1, b1, W2, b2, W3, b3, (float*)d_out);
}

// round 3
// speedup vs baseline: 1.6739x; 1.4845x over previous
#include <cuda_runtime.h>
#include <stdint.h>

// Problem constants (fixed by the dataset)
#define NN 50000
#define EE 800000
#define HH 3
#define OO 64
#define FT 192   // HH*OO

// ---------------- scratch (device globals; allocation-free) ----------------
__device__ __align__(16) float g_fs[(size_t)NN * FT];
__device__ __align__(16) float g_fd[(size_t)NN * FT];
__device__ __align__(16) float g_ha[(size_t)NN * FT];
__device__ __align__(16) float g_hb[(size_t)NN * FT];
__device__ __align__(16) float g_elog[(size_t)EE * HH];
__device__ int g_deg[NN];
__device__ int g_off[NN + 1];
__device__ int g_cur[NN];
__device__ int g_ss[EE];         // src ids sorted by dst
__device__ __align__(16) float g_pool[128 * OO];
__device__ __align__(16) float g_cnt[128];

__device__ __forceinline__ float lrelu(float x, float s) { return x > 0.f ? x : s * x; }

__device__ __forceinline__ uint32_t f2tf32(float f) {
    uint32_t u;
    asm("cvt.rna.tf32.f32 %0, %1;" : "=r"(u) : "f"(f));
    return u;
}

// ---------------- CSR construction (counting sort by dst) ----------------
__global__ void hist_kernel(const int* __restrict__ dst, int* __restrict__ deg, int E) {
    int e = blockIdx.x * blockDim.x + threadIdx.x;
    if (e < E) atomicAdd(&deg[dst[e]], 1);
}

__global__ void scan_kernel(const int* __restrict__ deg, int* __restrict__ off,
                            int* __restrict__ cur, int N, int E) {
    __shared__ int ssum[1024];
    int t = threadIdx.x;
    const int CH = (N + 1023) / 1024;
    int a = t * CH;
    int b = a + CH < N ? a + CH : N;
    int s = 0;
    for (int i = a; i < b; i++) s += deg[i];
    ssum[t] = s;
    __syncthreads();
    #pragma unroll
    for (int o = 1; o < 1024; o <<= 1) {
        int v = (t >= o) ? ssum[t - o] : 0;
        __syncthreads();
        ssum[t] += v;
        __syncthreads();
    }
    int base = (t == 0) ? 0 : ssum[t - 1];
    for (int i = a; i < b; i++) {
        off[i] = base; cur[i] = base; base += deg[i];
    }
    if (t == 1023) off[N] = E;
}

__global__ void scatter_kernel(const int* __restrict__ src, const int* __restrict__ dst,
                               int* __restrict__ cur, int* __restrict__ ss, int E) {
    int e = blockIdx.x * blockDim.x + threadIdx.x;
    if (e >= E) return;
    int p = atomicAdd(&cur[dst[e]], 1);
    ss[p] = src[e];
}

// ---------------- TF32 tensor-core GEMM (unchanged from R2) ----------------
#define GBM 128
#define GBN 64
#define GBK 32
#define ASTR 136   // 136 % 32 == 8
#define BSTR 72    // 72  % 32 == 8

__global__ __launch_bounds__(256) void gemm_tf32(
    const float* __restrict__ A, const float* __restrict__ W,
    const float* __restrict__ bias, float* __restrict__ C,
    int M, int K, int Nc)
{
    __shared__ uint32_t As[GBK][ASTR];   // [k][m]
    __shared__ uint32_t Bs[GBK][BSTR];   // [k][n]

    const int tid  = threadIdx.x;
    const int wid  = tid >> 5;
    const int lane = tid & 31;
    const int warpM = wid >> 1;
    const int warpN = wid & 1;
    const int gid = lane >> 2;
    const int tig = lane & 3;
    const int row0 = blockIdx.y * GBM;
    const int col0 = blockIdx.x * GBN;

    float c[2][4][4] = {};

    for (int k0 = 0; k0 < K; k0 += GBK) {
        #pragma unroll
        for (int p = 0; p < 4; p++) {
            int r = p * 32 + lane;
            int grow = row0 + r;
            float4 v = make_float4(0.f, 0.f, 0.f, 0.f);
            if (grow < M) v = *(const float4*)(A + (size_t)grow * K + k0 + wid * 4);
            As[wid * 4 + 0][r] = f2tf32(v.x);
            As[wid * 4 + 1][r] = f2tf32(v.y);
            As[wid * 4 + 2][r] = f2tf32(v.z);
            As[wid * 4 + 3][r] = f2tf32(v.w);
        }
        #pragma unroll
        for (int p = 0; p < 2; p++) {
            int n4 = wid + 8 * p;
            float4 v = *(const float4*)(W + (size_t)(k0 + lane) * Nc + col0 + n4 * 4);
            Bs[lane][n4 * 4 + 0] = f2tf32(v.x);
            Bs[lane][n4 * 4 + 1] = f2tf32(v.y);
            Bs[lane][n4 * 4 + 2] = f2tf32(v.z);
            Bs[lane][n4 * 4 + 3] = f2tf32(v.w);
        }
        __syncthreads();

        #pragma unroll
        for (int ks = 0; ks < 4; ks++) {
            const int kk = ks * 8;
            uint32_t a[2][4], b[4][2];
            #pragma unroll
            for (int mi = 0; mi < 2; mi++) {
                int rb = warpM * 32 + mi * 16;
                a[mi][0] = As[kk + tig][rb + gid];
                a[mi][1] = As[kk + tig][rb + gid + 8];
                a[mi][2] = As[kk + tig + 4][rb + gid];
                a[mi][3] = As[kk + tig + 4][rb + gid + 8];
            }
            #pragma unroll
            for (int ni = 0; ni < 4; ni++) {
                int cb = warpN * 32 + ni * 8;
                b[ni][0] = Bs[kk + tig][cb + gid];
                b[ni][1] = Bs[kk + tig + 4][cb + gid];
            }
            #pragma unroll
            for (int mi = 0; mi < 2; mi++)
                #pragma unroll
                for (int ni = 0; ni < 4; ni++)
                    asm volatile(
                        "mma.sync.aligned.m16n8k8.row.col.f32.tf32.tf32.f32 "
                        "{%0,%1,%2,%3}, {%4,%5,%6,%7}, {%8,%9}, {%0,%1,%2,%3};"
                        : "+f"(c[mi][ni][0]), "+f"(c[mi][ni][1]),
                          "+f"(c[mi][ni][2]), "+f"(c[mi][ni][3])
                        : "r"(a[mi][0]), "r"(a[mi][1]), "r"(a[mi][2]), "r"(a[mi][3]),
                          "r"(b[ni][0]), "r"(b[ni][1]));
        }
        __syncthreads();
    }

    #pragma unroll
    for (int mi = 0; mi < 2; mi++) {
        #pragma unroll
        for (int ni = 0; ni < 4; ni++) {
            int gcol = col0 + warpN * 32 + ni * 8 + tig * 2;
            float bx = bias[gcol], by = bias[gcol + 1];
            int r0 = row0 + warpM * 32 + mi * 16 + gid;
            if (r0 < M) {
                float2 o = make_float2(c[mi][ni][0] + bx, c[mi][ni][1] + by);
                *(float2*)(C + (size_t)r0 * Nc + gcol) = o;
            }
            int r1 = r0 + 8;
            if (r1 < M) {
                float2 o = make_float2(c[mi][ni][2] + bx, c[mi][ni][3] + by);
                *(float2*)(C + (size_t)r1 * Nc + gcol) = o;
            }
        }
    }
}

// ---------------- fused GATv2 edge phase: one warp per dst node ----------------
// pass 1: logits + running max; pass 2: exp + den (lane-parallel);
// pass 3: weighted aggregation. No atomics, no memsets.
// Element layout per lane: j*32+lane, j=0..5; head = j>>1.
__global__ __launch_bounds__(256) void gat_fused_kernel(
    const float* __restrict__ fs, const float* __restrict__ fd,
    const int* __restrict__ off, const int* __restrict__ ss,
    const float* __restrict__ attn, float* __restrict__ elog,
    float* __restrict__ hout, int N)
{
    __shared__ float sattn[FT];
    int t = threadIdx.x;
    if (t < FT) sattn[t] = attn[t];
    __syncthreads();

    int node = blockIdx.x * (blockDim.x >> 5) + (t >> 5);
    int lane = t & 31;
    if (node >= N) return;
    int e0 = off[node], e1 = off[node + 1];

    float fdv[6], av[6];
    #pragma unroll
    for (int j = 0; j < 6; j++) {
        fdv[j] = fd[(size_t)node * FT + j * 32 + lane];
        av[j]  = sattn[j * 32 + lane];
    }

    // ---- pass 1: logits, store to elog, running max
    float mx0 = -3.0e38f, mx1 = -3.0e38f, mx2 = -3.0e38f;
    for (int e = e0; e < e1; e++) {
        int s = ss[e];
        const float* p = fs + (size_t)s * FT;
        float t0 = 0.f, t1 = 0.f, t2 = 0.f;
        #pragma unroll
        for (int j = 0; j < 6; j++) {
            float v = p[j * 32 + lane] + fdv[j];
            v = v > 0.f ? v : 0.2f * v;
            float c = v * av[j];
            if (j < 2) t0 += c; else if (j < 4) t1 += c; else t2 += c;
        }
        #pragma unroll
        for (int o = 16; o; o >>= 1) {
            t0 += __shfl_xor_sync(0xffffffffu, t0, o);
            t1 += __shfl_xor_sync(0xffffffffu, t1, o);
            t2 += __shfl_xor_sync(0xffffffffu, t2, o);
        }
        if (lane < 3) elog[(size_t)e * 3 + lane] = (lane == 0 ? t0 : (lane == 1 ? t1 : t2));
        mx0 = fmaxf(mx0, t0); mx1 = fmaxf(mx1, t1); mx2 = fmaxf(mx2, t2);
    }
    __syncwarp();

    // ---- pass 2: exp + denominator (lane-parallel over edges)
    float d0 = 0.f, d1 = 0.f, d2 = 0.f;
    for (int e = e0 + lane; e < e1; e += 32) {
        float l0 = elog[(size_t)e * 3 + 0];
        float l1 = elog[(size_t)e * 3 + 1];
        float l2 = elog[(size_t)e * 3 + 2];
        l0 = __expf(l0 - mx0); l1 = __expf(l1 - mx1); l2 = __expf(l2 - mx2);
        elog[(size_t)e * 3 + 0] = l0;
        elog[(size_t)e * 3 + 1] = l1;
        elog[(size_t)e * 3 + 2] = l2;
        d0 += l0; d1 += l1; d2 += l2;
    }
    #pragma unroll
    for (int o = 16; o; o >>= 1) {
        d0 += __shfl_xor_sync(0xffffffffu, d0, o);
        d1 += __shfl_xor_sync(0xffffffffu, d1, o);
        d2 += __shfl_xor_sync(0xffffffffu, d2, o);
    }
    float r0 = 1.f / fmaxf(d0, 1e-9f);
    float r1 = 1.f / fmaxf(d1, 1e-9f);
    float r2 = 1.f / fmaxf(d2, 1e-9f);
    __syncwarp();

    // ---- pass 3: weighted aggregation
    float acc[6] = {};
    for (int e = e0; e < e1; e++) {
        int s = ss[e];
        float w0 = elog[(size_t)e * 3 + 0] * r0;   // broadcast loads
        float w1 = elog[(size_t)e * 3 + 1] * r1;
        float w2 = elog[(size_t)e * 3 + 2] * r2;
        const float* p = fs + (size_t)s * FT;
        #pragma unroll
        for (int j = 0; j < 6; j++) {
            float w = (j < 2) ? w0 : ((j < 4) ? w1 : w2);
            acc[j] = fmaf(w, p[j * 32 + lane], acc[j]);
        }
    }
    #pragma unroll
    for (int j = 0; j < 6; j++)
        hout[(size_t)node * FT + j * 32 + lane] = acc[j];
}

// ---------------- head-mean + per-graph pooling ----------------
__global__ void pool_kernel(const float* __restrict__ h, const int* __restrict__ gid,
                            float* __restrict__ pool, float* __restrict__ cnt, int N) {
    int idx = blockIdx.x * blockDim.x + threadIdx.x;
    if (idx >= N * OO) return;
    int n = idx >> 6, k = idx & 63;
    const float* p = h + (size_t)n * FT;
    float v = (p[k] + p[64 + k] + p[128 + k]) * (1.0f / 3.0f);
    int g = gid[n];
    atomicAdd(&pool[g * OO + k], v);
    if (k == 0) atomicAdd(&cnt[g], 1.0f);
}

// ---------------- final MLP: 64 -> 64 -> 32 -> 2, leaky 0.01 ----------------
__global__ void mlp_kernel(const float* __restrict__ pool, const float* __restrict__ cnt,
                           const float* __restrict__ W1, const float* __restrict__ b1,
                           const float* __restrict__ W2, const float* __restrict__ b2,
                           const float* __restrict__ W3, const float* __restrict__ b3,
                           float* __restrict__ out) {
    int g = blockIdx.x;
    int j = threadIdx.x;  // 64 threads
    __shared__ float gv[64], t1[64], t2[32];
    float c = fmaxf(cnt[g], 1.0f);
    gv[j] = pool[g * OO + j] / c;
    __syncthreads();
    float a = b1[j];
    #pragma unroll 8
    for (int k = 0; k < 64; k++) a = fmaf(gv[k], W1[k * 64 + j], a);
    t1[j] = lrelu(a, 0.01f);
    __syncthreads();
    if (j < 32) {
        float a2 = b2[j];
        #pragma unroll 8
        for (int k = 0; k < 64; k++) a2 = fmaf(t1[k], W2[k * 32 + j], a2);
        t2[j] = lrelu(a2, 0.01f);
    }
    __syncthreads();
    if (j < 2) {
        float a3 = b3[j];
        #pragma unroll
        for (int k = 0; k < 32; k++) a3 = fmaf(t2[k], W3[k * 2 + j], a3);
        out[g * 2 + j] = lrelu(a3, 0.01f);
    }
}

// ---------------- launcher ----------------
extern "C" void kernel_launch(void* const* d_in, const int* in_sizes, int n_in,
                              void* d_out, int out_size) {
    const float* x   = (const float*)d_in[0];
    const int*   src = (const int*)d_in[1];
    const int*   dst = (const int*)d_in[2];
    const int*   gid = (const int*)d_in[3];
    const float* Wsrc[3] = {(const float*)d_in[5],  (const float*)d_in[10], (const float*)d_in[15]};
    const float* bsrc[3] = {(const float*)d_in[6],  (const float*)d_in[11], (const float*)d_in[16]};
    const float* Wdst[3] = {(const float*)d_in[7],  (const float*)d_in[12], (const float*)d_in[17]};
    const float* bdst[3] = {(const float*)d_in[8],  (const float*)d_in[13], (const float*)d_in[18]};
    const float* attn[3] = {(const float*)d_in[9],  (const float*)d_in[14], (const float*)d_in[19]};
    const float* W1 = (const float*)d_in[20];
    const float* b1 = (const float*)d_in[21];
    const float* W2 = (const float*)d_in[22];
    const float* b2 = (const float*)d_in[23];
    const float* W3 = (const float*)d_in[24];
    const float* b3 = (const float*)d_in[25];

    const int N  = in_sizes[0] / 128;
    const int E  = in_sizes[1];
    const int ng = out_size / 2;

    float *fs, *fd, *ha, *hb, *elog, *pool, *cnt;
    int *deg, *off, *cur, *ssorted;
    cudaGetSymbolAddress((void**)&fs,   g_fs);
    cudaGetSymbolAddress((void**)&fd,   g_fd);
    cudaGetSymbolAddress((void**)&ha,   g_ha);
    cudaGetSymbolAddress((void**)&hb,   g_hb);
    cudaGetSymbolAddress((void**)&elog, g_elog);
    cudaGetSymbolAddress((void**)&deg,  g_deg);
    cudaGetSymbolAddress((void**)&off,  g_off);
    cudaGetSymbolAddress((void**)&cur,  g_cur);
    cudaGetSymbolAddress((void**)&ssorted, g_ss);
    cudaGetSymbolAddress((void**)&pool, g_pool);
    cudaGetSymbolAddress((void**)&cnt,  g_cnt);

    // ---- CSR build (once; reused by all 3 layers)
    cudaMemsetAsync(deg, 0, (size_t)N * sizeof(int), 0);
    hist_kernel<<<(E + 255) / 256, 256>>>(dst, deg, E);
    scan_kernel<<<1, 1024>>>(deg, off, cur, N, E);
    scatter_kernel<<<(E + 255) / 256, 256>>>(src, dst, cur, ssorted, E);

    const float* hin = x;
    int Fin = 128;
    float* houts[3] = {ha, hb, ha};
    const int nodeBlocks = (N + 7) / 8;   // 8 warps/block, 1 warp/node

    for (int l = 0; l < 3; l++) {
        dim3 gg(FT / GBN, (N + GBM - 1) / GBM);
        gemm_tf32<<<gg, 256>>>(hin, Wsrc[l], bsrc[l], fs, N, Fin, FT);
        gemm_tf32<<<gg, 256>>>(hin, Wdst[l], bdst[l], fd, N, Fin, FT);
        gat_fused_kernel<<<nodeBlocks, 256>>>(fs, fd, off, ssorted, attn[l], elog,
                                              houts[l], N);
        hin = houts[l];
        Fin = FT;
    }

    cudaMemsetAsync(pool, 0, 128 * OO * sizeof(float), 0);
    cudaMemsetAsync(cnt,  0, 128 * sizeof(float), 0);
    pool_kernel<<<(N * OO + 255) / 256, 256>>>(hin, gid, pool, cnt, N);
    mlp_kernel<<<ng, 64>>>(pool, cnt, W1, b1, W2, b2, W3, b3, (float*)d_out);
}